// round 16
// baseline (speedup 1.0000x reference)
#include <cuda_runtime.h>

// Problem constants (fixed by the reference)
#define BB 8
#define NT 256
#define WHD 21
#define PP 441          // WHD*WHD
#define IMW 1024
#define ITERS 20
#define PTS 14          // points per lane in prologue/epilogue p-mapping

__global__ __launch_bounds__(32)
void mt_kernel(const float* __restrict__ track,
               const float* __restrict__ imgs,
               float* __restrict__ out)
{
    const int id = blockIdx.x;           // one warp per track
    const int b = id >> 8;               // id / NT (NT = 256)
    const int t = id & 255;

    const float* f0 = imgs + (size_t)b * 2 * IMW * IMW;   // frame 0 (H==W==1024)
    const float* f1 = f0 + (size_t)(IMW * IMW);           // frame 1

    __shared__ float sSec[PP + 16];      // 'second' in row-major (i*21+j) layout

    const int lane = threadIdx.x & 31;

    // per-lane shift state (uniform across the warp)
    float sx, sy;
    {
        const float SCALE = 21.0f / 1024.0f;   // exact in fp32
        sx = track[b * (NT * 2) + t * 2 + 0] / SCALE;
        sy = track[b * (NT * 2) + t * 2 + 1] / SCALE;
    }

    // zero sSec pad so masked lanes read harmless values
    #pragma unroll
    for (int k = lane; k < PP + 16; k += 32) sSec[k] = 0.0f;

    // general bilinear (exact reference clip-then-weight); cold paths
    auto bilinearG = [&](const float* __restrict__ f, float gxv, float gyv,
                         float ssx, float ssy) -> float {
        float x = (gxv + ssx) * 10.5f;   // WH*0.5
        float y = (gyv + ssy) * 10.5f;
        float fx = floorf(x);
        float fy = floorf(y);
        float x0 = fminf(fmaxf(fx,        0.0f), 1023.0f);
        float x1 = fminf(fmaxf(fx + 1.0f, 0.0f), 1023.0f);
        float y0 = fminf(fmaxf(fy,        0.0f), 1023.0f);
        float y1 = fminf(fmaxf(fy + 1.0f, 0.0f), 1023.0f);
        float wa = (y1 - y) * (x1 - x);
        float wb = (y1 - y) * (x  - x0);
        float wc = (y  - y0) * (x1 - x);
        float wd = (y  - y0) * (x  - x0);
        int xi0 = (int)x0, xi1 = (int)x1;
        const float* r0 = f + (int)y0 * IMW;
        const float* r1 = f + (int)y1 * IMW;
        return wa * __ldg(r0 + xi0) + wb * __ldg(r0 + xi1)
             + wc * __ldg(r1 + xi0) + wd * __ldg(r1 + xi1);
    };

    // prologue: 'second' (frame 1 at initial positions) -> out + sSec
    {
        float* o1 = out + ((((size_t)b * 2) + 1) * NT + t) * PP;
        #pragma unroll
        for (int k = 0; k < PTS; ++k) {
            if (k < PTS - 1 || lane < PP - 32 * (PTS - 1)) {   // p < PP
                const int p = lane + k * 32;
                const int i = p / WHD;
                const int j = p - i * WHD;
                const float gx = -1.0f + 0.1f * (float)j;
                const float gy = -1.0f + 0.1f * (float)i;
                float s = bilinearG(f1, gx, gy, sx, sy);
                o1[p]   = s;
                sSec[p] = s;
            }
        }
    }
    __syncwarp();      // sSec visible; never written again

    // per-lane column geometry (j = lane)
    const float gxl = -1.0f + 0.1f * (float)lane;   // exact grid x (fallback)
    const float gxs = gxl * 10.5f;                  // pre-scaled (fast path)

    for (int it = 0; it < ITERS; ++it) {
        // warp-uniform interior test, 2-px safety margin
        bool interior;
        {
            float xlo = (-1.0f + sx) * 10.5f, xhi = (1.0f + sx) * 10.5f;
            float ylo = (-1.0f + sy) * 10.5f, yhi = (1.0f + sy) * 10.5f;
            interior = (floorf(xlo) >= 2.0f) && (floorf(xhi) <= 1019.0f)
                    && (floorf(ylo) >= 2.0f) && (floorf(yhi) <= 1019.0f);
        }

        float v0 = 0.f, v1 = 0.f, v2 = 0.f, v3 = 0.f, v4 = 0.f;

        // rolling patch rows: u* = row r-1, m* = row r, c* = row r+1 (L/M/R = j-1/j/j+1)
        float uL = 0.f, uM = 0.f, uR = 0.f;
        float mL = 0.f, mM = 0.f, mR = 0.f;

        if (interior) {
            const float sxs = sx * 10.5f;
            const float sys = sy * 10.5f;
            // x-setup: uniform over rows, per-lane over columns
            float x   = gxs + sxs;
            float fx  = floorf(x);
            float dx0 = x - fx;             // exact
            float dx1 = (fx + 1.0f) - x;    // exact
            int  cbase = __shfl_sync(0xffffffffu, (int)fx, 0);
            int  s     = (int)fx - cbase;   // in [0,22] for lanes 0..20

            int   curTop = -0x40000000;
            float pixA = 0.f, pixB = 0.f;   // image rows top, top+1 (24 px wide)

            for (int i = 0; i <= WHD; ++i) {       // i == WHD: virtual zero row
                float cL = 0.f, cM = 0.f, cR = 0.f;
                if (i < WHD) {
                    float gysr = (-1.0f + 0.1f * (float)i) * 10.5f;
                    float y   = gysr + sys;
                    float fy  = floorf(y);
                    float dy0 = y - fy;
                    float dy1 = (fy + 1.0f) - y;
                    int top = (int)fy;
                    if (top != curTop) {           // warp-uniform branch
                        if (top == curTop + 1) {
                            pixA = pixB;
                            pixB = (lane < 24) ? __ldg(f0 + (top + 1) * IMW + cbase + lane) : 0.f;
                        } else {
                            pixA = (lane < 24) ? __ldg(f0 + top * IMW + cbase + lane) : 0.f;
                            pixB = (lane < 24) ? __ldg(f0 + (top + 1) * IMW + cbase + lane) : 0.f;
                        }
                        curTop = top;
                    }
                    float A0 = __shfl_sync(0xffffffffu, pixA, s);
                    float A1 = __shfl_sync(0xffffffffu, pixA, s + 1);
                    float B0 = __shfl_sync(0xffffffffu, pixB, s);
                    float B1 = __shfl_sync(0xffffffffu, pixB, s + 1);
                    float o = (dy1 * dx1) * A0 + (dy1 * dx0) * A1
                            + (dy0 * dx1) * B0 + (dy0 * dx0) * B1;
                    cM = (lane < WHD) ? o : 0.f;   // zero outside patch columns
                    float tl = __shfl_up_sync(0xffffffffu, cM, 1);
                    cL = (lane >= 1) ? tl : 0.f;   // j==0 left pad = 0
                    cR = __shfl_down_sync(0xffffffffu, cM, 1);  // lane20 pulls lane21's 0
                }
                if (i >= 1) {
                    const int r = i - 1;
                    // cross-correlation Sobel, reference grouping
                    float Ix = (uR - uL) + 2.0f * (mR - mL) + (cR - cL);
                    float Iy = (cL - uL) + 2.0f * (cM - uM) + (cR - uR);
                    float It = sSec[r * WHD + lane] - mM;
                    if (lane < WHD) {
                        v0 = fmaf(Ix, Ix, v0);
                        v1 = fmaf(Iy, Iy, v1);
                        v2 = fmaf(Ix, Iy, v2);
                        v3 = fmaf(Ix, It, v3);
                        v4 = fmaf(Iy, It, v4);
                    }
                }
                uL = mL; uM = mM; uR = mR;
                mL = cL; mM = cM; mR = cR;
            }
        } else {
            // exact general path, row-mapped (rare)
            for (int i = 0; i <= WHD; ++i) {
                float cL = 0.f, cM = 0.f, cR = 0.f;
                if (i < WHD) {
                    float gyr = -1.0f + 0.1f * (float)i;
                    float o = 0.f;
                    if (lane < WHD) o = bilinearG(f0, gxl, gyr, sx, sy);
                    cM = o;
                    float tl = __shfl_up_sync(0xffffffffu, cM, 1);
                    cL = (lane >= 1) ? tl : 0.f;
                    cR = __shfl_down_sync(0xffffffffu, cM, 1);
                }
                if (i >= 1) {
                    const int r = i - 1;
                    float Ix = (uR - uL) + 2.0f * (mR - mL) + (cR - cL);
                    float Iy = (cL - uL) + 2.0f * (cM - uM) + (cR - uR);
                    float It = sSec[r * WHD + lane] - mM;
                    if (lane < WHD) {
                        v0 = fmaf(Ix, Ix, v0);
                        v1 = fmaf(Iy, Iy, v1);
                        v2 = fmaf(Ix, Iy, v2);
                        v3 = fmaf(Ix, It, v3);
                        v4 = fmaf(Iy, It, v4);
                    }
                }
                uL = mL; uM = mM; uR = mR;
                mL = cL; mM = cM; mR = cR;
            }
        }

        // butterfly reduction: every lane gets the full sums
        #pragma unroll
        for (int off = 16; off; off >>= 1) {
            v0 += __shfl_xor_sync(0xffffffffu, v0, off);
            v1 += __shfl_xor_sync(0xffffffffu, v1, off);
            v2 += __shfl_xor_sync(0xffffffffu, v2, off);
            v3 += __shfl_xor_sync(0xffffffffu, v3, off);
            v4 += __shfl_xor_sync(0xffffffffu, v4, off);
        }

        // 2x2 solve (every lane, identical)
        float det_inv = 1.0f / (v0 * v1 - v2 * v2);
        float Vx = det_inv * (v1    * (-v3) + (-v2) * (-v4));
        float Vy = det_inv * ((-v2) * (-v3) + v0    * (-v4));
        sx = sx - Vx;
        sy = sy - Vy;
    }

    // epilogue: final frame-0 sample at converged positions (exact path)
    {
        float* o0p = out + ((((size_t)b * 2) + 0) * NT + t) * PP;
        #pragma unroll
        for (int k = 0; k < PTS; ++k) {
            if (k < PTS - 1 || lane < PP - 32 * (PTS - 1)) {
                const int p = lane + k * 32;
                const int i = p / WHD;
                const int j = p - i * WHD;
                const float gx = -1.0f + 0.1f * (float)j;
                const float gy = -1.0f + 0.1f * (float)i;
                o0p[p] = bilinearG(f0, gx, gy, sx, sy);
            }
        }
    }
}

extern "C" void kernel_launch(void* const* d_in, const int* in_sizes, int n_in,
                              void* d_out, int out_size)
{
    // track_locs: 8*512 = 4096 floats; imgs: 8*2*1024*1024 floats.
    const float* track;
    const float* imgs;
    if (in_sizes[0] < in_sizes[1]) {
        track = (const float*)d_in[0];
        imgs  = (const float*)d_in[1];
    } else {
        track = (const float*)d_in[1];
        imgs  = (const float*)d_in[0];
    }
    float* out = (float*)d_out;
    mt_kernel<<<BB * NT, 32>>>(track, imgs, out);
}

// round 17
// speedup vs baseline: 1.8057x; 1.8057x over previous
#include <cuda_runtime.h>

// Problem constants (fixed by the reference)
#define BB 8
#define NT 256
#define WHD 21
#define PP 441          // WHD*WHD
#define PAD 23          // zero-padded patch dim
#define IMW 1024
#define ITERS 20
#define PTS 14          // points per lane: 32*14 = 448 >= 441

__global__ __launch_bounds__(32)
void mt_kernel(const float* __restrict__ track,
               const float* __restrict__ imgs,
               float* __restrict__ out)
{
    const int id = blockIdx.x;           // one warp per track
    const int b = id >> 8;               // id / NT (NT = 256)
    const int t = id & 255;

    const float* f0 = imgs + (size_t)b * 2 * IMW * IMW;   // frame 0 (H==W==1024)
    const float* f1 = f0 + (size_t)(IMW * IMW);           // frame 1

    __shared__ float sP[PAD * PAD];      // zero-padded sampled patch (warp-private)

    const int lane = threadIdx.x & 31;   // bounded -> guards fold for k<13

    // per-lane shift state (uniform across the warp)
    float sx, sy;
    {
        const float SCALE = 21.0f / 1024.0f;   // exact in fp32
        sx = track[b * (NT * 2) + t * 2 + 0] / SCALE;
        sy = track[b * (NT * 2) + t * 2 + 1] / SCALE;
    }

    // zero the padded patch once; border stays zero forever
    #pragma unroll
    for (int k = lane; k < PAD * PAD; k += 32) sP[k] = 0.0f;

    // ---- hoisted per-k geometry ----
    float gxs[PTS], gys[PTS];    // grid coords pre-scaled by 10.5 (fast path)
    int   pb[PTS];               // padded-patch index
    #pragma unroll
    for (int k = 0; k < PTS; ++k) {
        const int p = lane + k * 32;
        const int i = p / WHD;
        const int j = p - i * WHD;
        gxs[k] = (-1.0f + 0.1f * (float)j) * 10.5f;
        gys[k] = (-1.0f + 0.1f * (float)i) * 10.5f;
        pb[k] = (i + 1) * PAD + (j + 1);
    }

    // general bilinear (exact reference clip-then-weight); cold paths
    auto bilinearG = [&](const float* __restrict__ f, float gxv, float gyv,
                         float ssx, float ssy) -> float {
        float x = (gxv + ssx) * 10.5f;   // WH*0.5
        float y = (gyv + ssy) * 10.5f;
        float fx = floorf(x);
        float fy = floorf(y);
        float x0 = fminf(fmaxf(fx,        0.0f), 1023.0f);
        float x1 = fminf(fmaxf(fx + 1.0f, 0.0f), 1023.0f);
        float y0 = fminf(fmaxf(fy,        0.0f), 1023.0f);
        float y1 = fminf(fmaxf(fy + 1.0f, 0.0f), 1023.0f);
        float wa = (y1 - y) * (x1 - x);
        float wb = (y1 - y) * (x  - x0);
        float wc = (y  - y0) * (x1 - x);
        float wd = (y  - y0) * (x  - x0);
        int xi0 = (int)x0, xi1 = (int)x1;
        const float* r0 = f + (int)y0 * IMW;
        const float* r1 = f + (int)y1 * IMW;
        return wa * __ldg(r0 + xi0) + wb * __ldg(r0 + xi1)
             + wc * __ldg(r1 + xi0) + wd * __ldg(r1 + xi1);
    };

    // 'second' (frame 1 at initial positions) — fixed for all iterations
    float second[PTS];
    {
        float* o1 = out + ((((size_t)b * 2) + 1) * NT + t) * PP;
        #pragma unroll
        for (int k = 0; k < PTS; ++k) {
            second[k] = 0.0f;
            if (k < PTS - 1 || lane < PP - 32 * (PTS - 1)) {   // p < PP
                const int p = lane + k * 32;
                const int i = p / WHD;
                const int j = p - i * WHD;
                const float gx = -1.0f + 0.1f * (float)j;
                const float gy = -1.0f + 0.1f * (float)i;
                second[k] = bilinearG(f1, gx, gy, sx, sy);
                o1[p] = second[k];
            }
        }
    }

    for (int it = 0; it < ITERS; ++it) {
        // ---- warp-uniform interior test with 1-px safety margin ----
        bool interior;
        {
            float xlo = (-1.0f + sx) * 10.5f, xhi = (1.0f + sx) * 10.5f;
            float ylo = (-1.0f + sy) * 10.5f, yhi = (1.0f + sy) * 10.5f;
            interior = (floorf(xlo) >= 1.0f) && (floorf(xhi) + 2.0f <= 1023.0f)
                    && (floorf(ylo) >= 1.0f) && (floorf(yhi) + 2.0f <= 1023.0f);
        }

        // ---- sample f0 ----
        float o0[PTS];
        if (interior) {
            const float sxs = sx * 10.5f;
            const float sys = sy * 10.5f;
            // ks 0..12: all 32 lanes active -> neighbor-sharing via shuffles.
            #pragma unroll
            for (int k = 0; k < PTS - 1; ++k) {
                float x  = gxs[k] + sxs;
                float y  = gys[k] + sys;
                float fx = floorf(x);
                float fy = floorf(y);
                float dx0 = x - fx;             // exact
                float dy0 = y - fy;             // exact
                float dx1 = (fx + 1.0f) - x;    // exact
                float dy1 = (fy + 1.0f) - y;
                int ix  = (int)fx;
                int idx = (int)fmaf(fy, 1024.0f, fx);   // exact (< 2^20)
                const float* base = f0 + idx;
                float A0 = __ldg(base);                 // (y0, x0)
                float B0 = __ldg(base + IMW);           // (y1, x0)
                // lane+1 (same patch row) holds pixel (y0, x0+1) when its
                // ix is exactly ix+1; row wraps / gap-2 / lane31 fall back.
                int  nx    = __shfl_down_sync(0xffffffffu, ix, 1);
                bool extra = (lane == 31) || (nx != ix + 1);
                float A1 = __shfl_down_sync(0xffffffffu, A0, 1);
                float B1 = __shfl_down_sync(0xffffffffu, B0, 1);
                if (extra) {
                    A1 = __ldg(base + 1);
                    B1 = __ldg(base + IMW + 1);
                }
                o0[k] = (dy1 * dx1) * A0 + (dy1 * dx0) * A1
                      + (dy0 * dx1) * B0 + (dy0 * dx0) * B1;
                sP[pb[k]] = o0[k];
            }
            // k = 13: partial warp, guarded 4-LDG path (no shuffles)
            {
                const int k = PTS - 1;
                if (lane < PP - 32 * (PTS - 1)) {
                    float x  = gxs[k] + sxs;
                    float y  = gys[k] + sys;
                    float fx = floorf(x);
                    float fy = floorf(y);
                    float dx0 = x - fx;
                    float dy0 = y - fy;
                    float dx1 = (fx + 1.0f) - x;
                    float dy1 = (fy + 1.0f) - y;
                    int idx = (int)fmaf(fy, 1024.0f, fx);
                    const float* base = f0 + idx;
                    o0[k] = (dy1 * dx1) * __ldg(base)
                          + (dy1 * dx0) * __ldg(base + 1)
                          + (dy0 * dx1) * __ldg(base + IMW)
                          + (dy0 * dx0) * __ldg(base + IMW + 1);
                    sP[pb[k]] = o0[k];
                }
            }
        } else {
            #pragma unroll
            for (int k = 0; k < PTS; ++k) {
                if (k < PTS - 1 || lane < PP - 32 * (PTS - 1)) {
                    const int p = lane + k * 32;
                    const int i = p / WHD;
                    const int j = p - i * WHD;
                    const float gx = -1.0f + 0.1f * (float)j;
                    const float gy = -1.0f + 0.1f * (float)i;
                    o0[k] = bilinearG(f0, gx, gy, sx, sy);
                    sP[pb[k]] = o0[k];
                }
            }
        }
        __syncwarp();                    // patch writes visible to stencil reads

        // ---- per-point zero-padded Sobel stencil + local accumulation ----
        float v0 = 0.f, v1 = 0.f, v2 = 0.f, v3 = 0.f, v4 = 0.f;
        #pragma unroll
        for (int k = 0; k < PTS; ++k) {
            if (k < PTS - 1 || lane < PP - 32 * (PTS - 1)) {
                const int pc = pb[k];
                float a00 = sP[pc - PAD - 1], a01 = sP[pc - PAD], a02 = sP[pc - PAD + 1];
                float a10 = sP[pc - 1],                            a12 = sP[pc + 1];
                float a20 = sP[pc + PAD - 1], a21 = sP[pc + PAD], a22 = sP[pc + PAD + 1];
                float Ix = (a02 - a00) + 2.0f * (a12 - a10) + (a22 - a20);
                float Iy = (a20 - a00) + 2.0f * (a21 - a01) + (a22 - a02);
                float It = second[k] - o0[k];
                v0 = fmaf(Ix, Ix, v0);
                v1 = fmaf(Iy, Iy, v1);
                v2 = fmaf(Ix, Iy, v2);
                v3 = fmaf(Ix, It, v3);
                v4 = fmaf(Iy, It, v4);
            }
        }

        // ---- butterfly reduction: every lane ends with the full sums ----
        #pragma unroll
        for (int off = 16; off; off >>= 1) {
            v0 += __shfl_xor_sync(0xffffffffu, v0, off);
            v1 += __shfl_xor_sync(0xffffffffu, v1, off);
            v2 += __shfl_xor_sync(0xffffffffu, v2, off);
            v3 += __shfl_xor_sync(0xffffffffu, v3, off);
            v4 += __shfl_xor_sync(0xffffffffu, v4, off);
        }

        // ---- 2x2 solve (every lane, identical) ----
        float det_inv = 1.0f / (v0 * v1 - v2 * v2);
        float Vx = det_inv * (v1    * (-v3) + (-v2) * (-v4));
        float Vy = det_inv * ((-v2) * (-v3) + v0    * (-v4));
        sx = sx - Vx;
        sy = sy - Vy;
    }

    // final sample of frame 0 at converged positions (exact general path)
    {
        float* o0p = out + ((((size_t)b * 2) + 0) * NT + t) * PP;
        #pragma unroll
        for (int k = 0; k < PTS; ++k) {
            if (k < PTS - 1 || lane < PP - 32 * (PTS - 1)) {
                const int p = lane + k * 32;
                const int i = p / WHD;
                const int j = p - i * WHD;
                const float gx = -1.0f + 0.1f * (float)j;
                const float gy = -1.0f + 0.1f * (float)i;
                o0p[p] = bilinearG(f0, gx, gy, sx, sy);
            }
        }
    }
}

extern "C" void kernel_launch(void* const* d_in, const int* in_sizes, int n_in,
                              void* d_out, int out_size)
{
    // track_locs: 8*512 = 4096 floats; imgs: 8*2*1024*1024 floats.
    const float* track;
    const float* imgs;
    if (in_sizes[0] < in_sizes[1]) {
        track = (const float*)d_in[0];
        imgs  = (const float*)d_in[1];
    } else {
        track = (const float*)d_in[1];
        imgs  = (const float*)d_in[0];
    }
    float* out = (float*)d_out;
    mt_kernel<<<BB * NT, 32>>>(track, imgs, out);
}